// round 1
// baseline (speedup 1.0000x reference)
#include <cuda_runtime.h>
#include <cstdint>

#define N_NODES 50000
#define N_EDGES 600000
#define IN_F    128
#define H_F     256

// ---------------- scratch (static device globals; no allocation) -------------
__device__ float g_deg_out[N_NODES];
__device__ float g_deg_in[N_NODES];
__device__ float g_norm_src[N_NODES];
__device__ float g_norm_dst[N_NODES];
__device__ float g_agg[(size_t)N_NODES * IN_F];
__device__ float g_h1[(size_t)N_NODES * H_F];
__device__ float g_h2[(size_t)N_NODES * H_F];

// ---------------- zero scratch (agg + degrees) --------------------------------
__global__ void zero_kernel() {
    const int total = N_NODES * IN_F;
    for (int i = blockIdx.x * blockDim.x + threadIdx.x; i < total;
         i += gridDim.x * blockDim.x) {
        g_agg[i] = 0.0f;
        if (i < N_NODES) { g_deg_out[i] = 0.0f; g_deg_in[i] = 0.0f; }
    }
}

// ---------------- degree accumulation ----------------------------------------
__global__ void degree_kernel(const int* __restrict__ src,
                              const int* __restrict__ dst) {
    int e = blockIdx.x * blockDim.x + threadIdx.x;
    if (e >= N_EDGES) return;
    atomicAdd(&g_deg_out[src[e]], 1.0f);
    atomicAdd(&g_deg_in[dst[e]], 1.0f);
}

// ---------------- norms -------------------------------------------------------
__global__ void norm_kernel() {
    int i = blockIdx.x * blockDim.x + threadIdx.x;
    if (i >= N_NODES) return;
    g_norm_src[i] = rsqrtf(fmaxf(g_deg_out[i], 1.0f));
    g_norm_dst[i] = rsqrtf(fmaxf(g_deg_in[i], 1.0f));
}

// ---------------- SpMM scatter: agg[dst] += x[src] * norm_src[src] -----------
// One warp per edge; each lane handles 4 contiguous floats (float4 load,
// 4 scalar REDG atomics).
__global__ __launch_bounds__(256) void scatter_kernel(
    const float* __restrict__ x,
    const int* __restrict__ src,
    const int* __restrict__ dst)
{
    int warp = (blockIdx.x * blockDim.x + threadIdx.x) >> 5;
    int lane = threadIdx.x & 31;
    if (warp >= N_EDGES) return;
    int s = src[warp];
    int d = dst[warp];
    float ns = g_norm_src[s];
    const float4* xrow = reinterpret_cast<const float4*>(x + (size_t)s * IN_F);
    float4 v = xrow[lane];
    float* aggrow = g_agg + (size_t)d * IN_F + lane * 4;
    atomicAdd(aggrow + 0, v.x * ns);
    atomicAdd(aggrow + 1, v.y * ns);
    atomicAdd(aggrow + 2, v.z * ns);
    atomicAdd(aggrow + 3, v.w * ns);
}

// ---------------- dense GEMM: C = op(A) @ B + bias ---------------------------
// op(A): optional relu, optional per-row scale (norm_dst).
// BM=128, BN=64, BK=16; 256 threads, 8x4 microtile per thread.
template <bool RELU_A, bool SCALE_A>
__global__ __launch_bounds__(256) void gemm_kernel(
    const float* __restrict__ A, const float* __restrict__ B,
    const float* __restrict__ bias, const float* __restrict__ rowscale,
    float* __restrict__ C, int M, int K, int NC)
{
    constexpr int BM = 128, BN = 64, BK = 16, TM = 8, TN = 4;
    __shared__ float As[BK][BM + 1];   // +1 pad: conflict-free transposed store
    __shared__ float Bs[BK][BN];

    const int tid = threadIdx.x;
    const int block_m = blockIdx.y * BM;
    const int block_n = blockIdx.x * BN;
    const int ty = tid / 16;   // 0..15 -> row group of TM
    const int tx = tid % 16;   // 0..15 -> col group of TN

    float acc[TM][TN] = {};

    for (int k0 = 0; k0 < K; k0 += BK) {
        // Load A tile (BM x BK), transposed into shared
        #pragma unroll
        for (int i = tid; i < BM * BK; i += 256) {
            int r = i / BK, c = i % BK;
            int gr = block_m + r;
            float v = 0.0f;
            if (gr < M) {
                v = A[(size_t)gr * K + k0 + c];
                if (RELU_A) v = fmaxf(v, 0.0f);
                if (SCALE_A) v *= rowscale[gr];
            }
            As[c][r] = v;
        }
        // Load B tile (BK x BN), row-major coalesced
        #pragma unroll
        for (int i = tid; i < BK * BN; i += 256) {
            int r = i / BN, c = i % BN;
            Bs[r][c] = B[(size_t)(k0 + r) * NC + block_n + c];
        }
        __syncthreads();

        #pragma unroll
        for (int k = 0; k < BK; k++) {
            float a[TM], b[TN];
            #pragma unroll
            for (int i = 0; i < TM; i++) a[i] = As[k][ty * TM + i];
            #pragma unroll
            for (int j = 0; j < TN; j++) b[j] = Bs[k][tx * TN + j];
            #pragma unroll
            for (int i = 0; i < TM; i++)
                #pragma unroll
                for (int j = 0; j < TN; j++)
                    acc[i][j] = fmaf(a[i], b[j], acc[i][j]);
        }
        __syncthreads();
    }

    #pragma unroll
    for (int i = 0; i < TM; i++) {
        int gr = block_m + ty * TM + i;
        if (gr >= M) continue;
        #pragma unroll
        for (int j = 0; j < TN; j++) {
            int gc = block_n + tx * TN + j;
            C[(size_t)gr * NC + gc] = acc[i][j] + bias[gc];
        }
    }
}

// ---------------- launch ------------------------------------------------------
extern "C" void kernel_launch(void* const* d_in, const int* in_sizes, int n_in,
                              void* d_out, int out_size)
{
    const float* x      = (const float*)d_in[0];   // [N, 128]
    const int*   src    = (const int*)  d_in[1];   // [E]
    const int*   dst    = (const int*)  d_in[2];   // [E]
    const float* W_conv = (const float*)d_in[3];   // [128, 256]
    const float* b_conv = (const float*)d_in[4];   // [256]
    const float* W_fc   = (const float*)d_in[5];   // [256, 256]
    const float* b_fc   = (const float*)d_in[6];   // [256]
    const float* W_fc2  = (const float*)d_in[7];   // [256, 256]
    const float* b_fc2  = (const float*)d_in[8];   // [256]
    float* out = (float*)d_out;                    // [N, 256]

    (void)in_sizes; (void)n_in; (void)out_size;

    // device-symbol addresses for scratch buffers used as GEMM operands
    float* agg_ptr;  cudaGetSymbolAddress((void**)&agg_ptr,  g_agg);
    float* h1_ptr;   cudaGetSymbolAddress((void**)&h1_ptr,   g_h1);
    float* h2_ptr;   cudaGetSymbolAddress((void**)&h2_ptr,   g_h2);
    float* nrm_ptr;  cudaGetSymbolAddress((void**)&nrm_ptr,  g_norm_dst);

    // 1) zero scratch (agg + degrees)
    zero_kernel<<<512, 256>>>();

    // 2) degrees
    degree_kernel<<<(N_EDGES + 255) / 256, 256>>>(src, dst);

    // 3) norms
    norm_kernel<<<(N_NODES + 255) / 256, 256>>>();

    // 4) SpMM scatter (one warp per edge)
    {
        int warps_per_block = 256 / 32;
        int blocks = (N_EDGES + warps_per_block - 1) / warps_per_block;
        scatter_kernel<<<blocks, 256>>>(x, src, dst);
    }

    // 5) h1 = (agg * norm_dst) @ W_conv + b_conv        [N,128]x[128,256]
    {
        dim3 grid((H_F + 63) / 64, (N_NODES + 127) / 128);
        gemm_kernel<false, true><<<grid, 256>>>(agg_ptr, W_conv, b_conv, nrm_ptr,
                                                h1_ptr, N_NODES, IN_F, H_F);
    }
    // 6) h2 = relu(h1) @ W_fc + b_fc                    [N,256]x[256,256]
    {
        dim3 grid((H_F + 63) / 64, (N_NODES + 127) / 128);
        gemm_kernel<true, false><<<grid, 256>>>(h1_ptr, W_fc, b_fc, nullptr,
                                                h2_ptr, N_NODES, H_F, H_F);
    }
    // 7) out = relu(h2) @ W_fc2 + b_fc2                 [N,256]x[256,256]
    {
        dim3 grid((H_F + 63) / 64, (N_NODES + 127) / 128);
        gemm_kernel<true, false><<<grid, 256>>>(h2_ptr, W_fc2, b_fc2, nullptr,
                                                out, N_NODES, H_F, H_F);
    }
}

// round 2
// speedup vs baseline: 2.4448x; 2.4448x over previous
#include <cuda_runtime.h>
#include <cstdint>

#define N_NODES 50000
#define N_EDGES 600000
#define IN_F    128
#define H_F     256

// ---------------- scratch (static device globals; no allocation) -------------
__device__ int   g_deg_out_i[N_NODES];
__device__ int   g_deg_in_i[N_NODES];
__device__ float g_norm_src[N_NODES];
__device__ float g_norm_dst[N_NODES];
__device__ int   g_row_ptr[N_NODES + 1];
__device__ int   g_cursor[N_NODES];
__device__ int   g_csr_src[N_EDGES];
__device__ float g_agg[(size_t)N_NODES * IN_F];
__device__ float g_h1[(size_t)N_NODES * H_F];
__device__ float g_h2[(size_t)N_NODES * H_F];

// ---------------- zero degree counters ----------------------------------------
__global__ void zero_kernel() {
    int i = blockIdx.x * blockDim.x + threadIdx.x;
    if (i < N_NODES) { g_deg_out_i[i] = 0; g_deg_in_i[i] = 0; }
}

// ---------------- degree accumulation (int atomics) ----------------------------
__global__ void degree_kernel(const int* __restrict__ src,
                              const int* __restrict__ dst) {
    int e = blockIdx.x * blockDim.x + threadIdx.x;
    if (e >= N_EDGES) return;
    atomicAdd(&g_deg_out_i[src[e]], 1);
    atomicAdd(&g_deg_in_i[dst[e]], 1);
}

// ---------------- norms -------------------------------------------------------
__global__ void norm_kernel() {
    int i = blockIdx.x * blockDim.x + threadIdx.x;
    if (i >= N_NODES) return;
    g_norm_src[i] = rsqrtf(fmaxf((float)g_deg_out_i[i], 1.0f));
    g_norm_dst[i] = rsqrtf(fmaxf((float)g_deg_in_i[i], 1.0f));
}

// ---------------- single-block prefix scan of deg_in -> row_ptr ---------------
__global__ void scan_kernel() {
    __shared__ int warp_sums[32];
    __shared__ int s_carry;
    int tid = threadIdx.x, lane = tid & 31, wid = tid >> 5;
    if (tid == 0) { s_carry = 0; g_row_ptr[0] = 0; }
    __syncthreads();
    for (int base = 0; base < N_NODES; base += 1024) {
        int i = base + tid;
        int v = (i < N_NODES) ? g_deg_in_i[i] : 0;
        int x = v;
        #pragma unroll
        for (int off = 1; off < 32; off <<= 1) {
            int t = __shfl_up_sync(0xffffffffu, x, off);
            if (lane >= off) x += t;
        }
        if (lane == 31) warp_sums[wid] = x;
        __syncthreads();
        if (wid == 0) {
            int w = warp_sums[lane];
            #pragma unroll
            for (int off = 1; off < 32; off <<= 1) {
                int t = __shfl_up_sync(0xffffffffu, w, off);
                if (lane >= off) w += t;
            }
            warp_sums[lane] = w;
        }
        __syncthreads();
        int incl = x + (wid > 0 ? warp_sums[wid - 1] : 0) + s_carry;
        if (i < N_NODES) g_row_ptr[i + 1] = incl;
        __syncthreads();
        if (tid == 1023) s_carry = incl;
        __syncthreads();
    }
}

// ---------------- cursor = row_ptr ---------------------------------------------
__global__ void cursor_kernel() {
    int i = blockIdx.x * blockDim.x + threadIdx.x;
    if (i < N_NODES) g_cursor[i] = g_row_ptr[i];
}

// ---------------- fill CSR (by dst) --------------------------------------------
__global__ void fill_kernel(const int* __restrict__ src,
                            const int* __restrict__ dst) {
    int e = blockIdx.x * blockDim.x + threadIdx.x;
    if (e >= N_EDGES) return;
    int pos = atomicAdd(&g_cursor[dst[e]], 1);
    g_csr_src[pos] = src[e];
}

// ---------------- gather SpMM: agg[d] = norm_dst[d] * sum x[s]*norm_src[s] ----
// one warp per dst node, lane handles 4 contiguous features (float4)
__global__ __launch_bounds__(256) void gather_kernel(const float* __restrict__ x)
{
    int warp = (blockIdx.x * blockDim.x + threadIdx.x) >> 5;
    int lane = threadIdx.x & 31;
    if (warp >= N_NODES) return;
    int beg = g_row_ptr[warp];
    int end = g_row_ptr[warp + 1];
    float4 acc = make_float4(0.f, 0.f, 0.f, 0.f);
    for (int j = beg; j < end; j++) {
        int s = g_csr_src[j];
        float ns = g_norm_src[s];
        float4 v = reinterpret_cast<const float4*>(x + (size_t)s * IN_F)[lane];
        acc.x = fmaf(v.x, ns, acc.x);
        acc.y = fmaf(v.y, ns, acc.y);
        acc.z = fmaf(v.z, ns, acc.z);
        acc.w = fmaf(v.w, ns, acc.w);
    }
    float nd = g_norm_dst[warp];
    acc.x *= nd; acc.y *= nd; acc.z *= nd; acc.w *= nd;
    reinterpret_cast<float4*>(g_agg + (size_t)warp * IN_F)[lane] = acc;
}

// ---------------- tf32 tensor-core GEMM: C = op(A) @ B + bias ------------------
// BM=128, BN=128, BK=32. 256 threads = 8 warps as 4(m) x 2(n); warp tile 32x64.
// mma.sync.aligned.m16n8k8 tf32, fp32 accumulate.
__device__ __forceinline__ uint32_t f2tf(float f) {
    uint32_t u;
    asm("cvt.rna.tf32.f32 %0, %1;" : "=r"(u) : "f"(f));
    return u;
}

template <bool RELU_A>
__global__ __launch_bounds__(256) void gemm_tf32(
    const float* __restrict__ A, const float* __restrict__ B,
    const float* __restrict__ bias, float* __restrict__ C,
    int M, int K, int NC)
{
    constexpr int BM = 128, BN = 128, BK = 32;
    constexpr int AS = BK + 4;    // 36-word row stride (conflict-free frag LDS)
    constexpr int BS = BN + 8;    // 136-word row stride
    __shared__ uint32_t As[BM * AS];   // 18432 B
    __shared__ uint32_t Bs[BK * BS];   // 17408 B

    const int tid  = threadIdx.x;
    const int lane = tid & 31;
    const int wrp  = tid >> 5;
    const int wm   = wrp & 3;          // 0..3: m offset wm*32
    const int wn   = wrp >> 2;         // 0..1: n offset wn*64
    const int gid  = lane >> 2;        // groupID 0..7
    const int tig  = lane & 3;         // threadID in group 0..3

    const int block_m = blockIdx.y * BM;
    const int block_n = blockIdx.x * BN;

    // global load mapping
    const int a_row = tid >> 3;        // 0..31, +32*i  (4 iters -> 128 rows)
    const int a_c4  = tid & 7;         // float4 column within BK=32
    const int b_row = tid >> 5;        // 0..7, +8*i   (4 iters -> 32 rows)
    const int b_c4  = tid & 31;        // float4 column within BN=128

    const int nchunks = K / BK;

    float acc[64];
    #pragma unroll
    for (int i = 0; i < 64; i++) acc[i] = 0.0f;

    float4 a_pref[4], b_pref[4];

    auto load_tile = [&](int k0) {
        #pragma unroll
        for (int i = 0; i < 4; i++) {
            int gr = block_m + a_row + i * 32;
            if (gr < M)
                a_pref[i] = reinterpret_cast<const float4*>(
                                A + (size_t)gr * K + k0)[a_c4];
            else
                a_pref[i] = make_float4(0.f, 0.f, 0.f, 0.f);
        }
        #pragma unroll
        for (int i = 0; i < 4; i++) {
            b_pref[i] = reinterpret_cast<const float4*>(
                            B + (size_t)(k0 + b_row + i * 8) * NC + block_n)[b_c4];
        }
    };

    auto store_tile = [&]() {
        #pragma unroll
        for (int i = 0; i < 4; i++) {
            float4 v = a_pref[i];
            if (RELU_A) {
                v.x = fmaxf(v.x, 0.f); v.y = fmaxf(v.y, 0.f);
                v.z = fmaxf(v.z, 0.f); v.w = fmaxf(v.w, 0.f);
            }
            uint4 u = make_uint4(f2tf(v.x), f2tf(v.y), f2tf(v.z), f2tf(v.w));
            *reinterpret_cast<uint4*>(&As[(a_row + i * 32) * AS + a_c4 * 4]) = u;
        }
        #pragma unroll
        for (int i = 0; i < 4; i++) {
            float4 v = b_pref[i];
            uint4 u = make_uint4(f2tf(v.x), f2tf(v.y), f2tf(v.z), f2tf(v.w));
            *reinterpret_cast<uint4*>(&Bs[(b_row + i * 8) * BS + b_c4 * 4]) = u;
        }
    };

    load_tile(0);

    for (int ch = 0; ch < nchunks; ch++) {
        store_tile();
        __syncthreads();
        if (ch + 1 < nchunks) load_tile((ch + 1) * BK);

        #pragma unroll
        for (int kq = 0; kq < 4; kq++) {
            uint32_t af[2][4];
            #pragma unroll
            for (int mt = 0; mt < 2; mt++) {
                int r = wm * 32 + mt * 16 + gid;
                int c = kq * 8 + tig;
                af[mt][0] = As[r * AS + c];
                af[mt][1] = As[(r + 8) * AS + c];
                af[mt][2] = As[r * AS + c + 4];
                af[mt][3] = As[(r + 8) * AS + c + 4];
            }
            uint32_t bf[8][2];
            #pragma unroll
            for (int nt = 0; nt < 8; nt++) {
                int cb = wn * 64 + nt * 8 + gid;
                int rb = kq * 8 + tig;
                bf[nt][0] = Bs[rb * BS + cb];
                bf[nt][1] = Bs[(rb + 4) * BS + cb];
            }
            #pragma unroll
            for (int mt = 0; mt < 2; mt++) {
                #pragma unroll
                for (int nt = 0; nt < 8; nt++) {
                    float* c = &acc[(mt * 8 + nt) * 4];
                    asm volatile(
                        "mma.sync.aligned.m16n8k8.row.col.f32.tf32.tf32.f32 "
                        "{%0,%1,%2,%3},{%4,%5,%6,%7},{%8,%9},{%0,%1,%2,%3};\n"
                        : "+f"(c[0]), "+f"(c[1]), "+f"(c[2]), "+f"(c[3])
                        : "r"(af[mt][0]), "r"(af[mt][1]),
                          "r"(af[mt][2]), "r"(af[mt][3]),
                          "r"(bf[nt][0]), "r"(bf[nt][1]));
                }
            }
        }
        __syncthreads();
    }

    // epilogue: bias add + store
    #pragma unroll
    for (int mt = 0; mt < 2; mt++) {
        int r0 = block_m + wm * 32 + mt * 16 + gid;
        #pragma unroll
        for (int nt = 0; nt < 8; nt++) {
            int gc = block_n + wn * 64 + nt * 8 + tig * 2;
            float bv0 = bias[gc], bv1 = bias[gc + 1];
            const float* c = &acc[(mt * 8 + nt) * 4];
            if (r0 < M) {
                C[(size_t)r0 * NC + gc]     = c[0] + bv0;
                C[(size_t)r0 * NC + gc + 1] = c[1] + bv1;
            }
            if (r0 + 8 < M) {
                C[(size_t)(r0 + 8) * NC + gc]     = c[2] + bv0;
                C[(size_t)(r0 + 8) * NC + gc + 1] = c[3] + bv1;
            }
        }
    }
}

// ---------------- launch ------------------------------------------------------
extern "C" void kernel_launch(void* const* d_in, const int* in_sizes, int n_in,
                              void* d_out, int out_size)
{
    const float* x      = (const float*)d_in[0];   // [N, 128]
    const int*   src    = (const int*)  d_in[1];   // [E]
    const int*   dst    = (const int*)  d_in[2];   // [E]
    const float* W_conv = (const float*)d_in[3];   // [128, 256]
    const float* b_conv = (const float*)d_in[4];   // [256]
    const float* W_fc   = (const float*)d_in[5];   // [256, 256]
    const float* b_fc   = (const float*)d_in[6];   // [256]
    const float* W_fc2  = (const float*)d_in[7];   // [256, 256]
    const float* b_fc2  = (const float*)d_in[8];   // [256]
    float* out = (float*)d_out;                    // [N, 256]

    (void)in_sizes; (void)n_in; (void)out_size;

    float* agg_ptr; cudaGetSymbolAddress((void**)&agg_ptr, g_agg);
    float* h1_ptr;  cudaGetSymbolAddress((void**)&h1_ptr,  g_h1);
    float* h2_ptr;  cudaGetSymbolAddress((void**)&h2_ptr,  g_h2);

    const int NB = (N_NODES + 255) / 256;
    const int EB = (N_EDGES + 255) / 256;

    zero_kernel<<<NB, 256>>>();
    degree_kernel<<<EB, 256>>>(src, dst);
    norm_kernel<<<NB, 256>>>();
    scan_kernel<<<1, 1024>>>();
    cursor_kernel<<<NB, 256>>>();
    fill_kernel<<<EB, 256>>>(src, dst);

    // SpMM gather: one warp per dst node (8 warps/block)
    gather_kernel<<<(N_NODES + 7) / 8, 256>>>(x);

    dim3 grid(H_F / 128, (N_NODES + 127) / 128);
    // h1 = agg @ W_conv + b_conv       (norm_dst already folded into agg)
    gemm_tf32<false><<<grid, 256>>>(agg_ptr, W_conv, b_conv, h1_ptr,
                                    N_NODES, IN_F, H_F);
    // h2 = relu(h1) @ W_fc + b_fc
    gemm_tf32<true><<<grid, 256>>>(h1_ptr, W_fc, b_fc, h2_ptr,
                                   N_NODES, H_F, H_F);
    // out = relu(h2) @ W_fc2 + b_fc2
    gemm_tf32<true><<<grid, 256>>>(h2_ptr, W_fc2, b_fc2, out,
                                   N_NODES, H_F, H_F);
}

// round 3
// speedup vs baseline: 2.4680x; 1.0095x over previous
#include <cuda_runtime.h>
#include <cstdint>

#define N_NODES 50000
#define N_EDGES 600000
#define IN_F    128
#define H_F     256

// ---------------- scratch (static device globals; no allocation) -------------
__device__ int   g_deg_out_i[N_NODES];
__device__ int   g_deg_in_i[N_NODES];
__device__ float g_norm_src[N_NODES];
__device__ float g_norm_dst[N_NODES];
__device__ int   g_row_ptr[N_NODES + 1];
__device__ int   g_cursor[N_NODES];
__device__ int   g_csr_src[N_EDGES];
__device__ float g_agg[(size_t)N_NODES * IN_F];
__device__ float g_h1[(size_t)N_NODES * H_F];
__device__ float g_h2[(size_t)N_NODES * H_F];

// ---------------- zero degree counters ----------------------------------------
__global__ void zero_kernel() {
    int i = blockIdx.x * blockDim.x + threadIdx.x;
    if (i < N_NODES) { g_deg_out_i[i] = 0; g_deg_in_i[i] = 0; }
}

// ---------------- degree accumulation (int atomics) ----------------------------
__global__ void degree_kernel(const int* __restrict__ src,
                              const int* __restrict__ dst) {
    int e = blockIdx.x * blockDim.x + threadIdx.x;
    if (e >= N_EDGES) return;
    atomicAdd(&g_deg_out_i[src[e]], 1);
    atomicAdd(&g_deg_in_i[dst[e]], 1);
}

// ---------------- norms -------------------------------------------------------
__global__ void norm_kernel() {
    int i = blockIdx.x * blockDim.x + threadIdx.x;
    if (i >= N_NODES) return;
    g_norm_src[i] = rsqrtf(fmaxf((float)g_deg_out_i[i], 1.0f));
    g_norm_dst[i] = rsqrtf(fmaxf((float)g_deg_in_i[i], 1.0f));
}

// ---------------- single-block prefix scan of deg_in -> row_ptr ---------------
__global__ void scan_kernel() {
    __shared__ int warp_sums[32];
    __shared__ int s_carry;
    int tid = threadIdx.x, lane = tid & 31, wid = tid >> 5;
    if (tid == 0) { s_carry = 0; g_row_ptr[0] = 0; }
    __syncthreads();
    for (int base = 0; base < N_NODES; base += 1024) {
        int i = base + tid;
        int v = (i < N_NODES) ? g_deg_in_i[i] : 0;
        int x = v;
        #pragma unroll
        for (int off = 1; off < 32; off <<= 1) {
            int t = __shfl_up_sync(0xffffffffu, x, off);
            if (lane >= off) x += t;
        }
        if (lane == 31) warp_sums[wid] = x;
        __syncthreads();
        if (wid == 0) {
            int w = warp_sums[lane];
            #pragma unroll
            for (int off = 1; off < 32; off <<= 1) {
                int t = __shfl_up_sync(0xffffffffu, w, off);
                if (lane >= off) w += t;
            }
            warp_sums[lane] = w;
        }
        __syncthreads();
        int incl = x + (wid > 0 ? warp_sums[wid - 1] : 0) + s_carry;
        if (i < N_NODES) g_row_ptr[i + 1] = incl;
        __syncthreads();
        if (tid == 1023) s_carry = incl;
        __syncthreads();
    }
}

// ---------------- cursor = row_ptr ---------------------------------------------
__global__ void cursor_kernel() {
    int i = blockIdx.x * blockDim.x + threadIdx.x;
    if (i < N_NODES) g_cursor[i] = g_row_ptr[i];
}

// ---------------- fill CSR (by dst) --------------------------------------------
__global__ void fill_kernel(const int* __restrict__ src,
                            const int* __restrict__ dst) {
    int e = blockIdx.x * blockDim.x + threadIdx.x;
    if (e >= N_EDGES) return;
    int pos = atomicAdd(&g_cursor[dst[e]], 1);
    g_csr_src[pos] = src[e];
}

// ---------------- gather SpMM: agg[d] = norm_dst[d] * sum x[s]*norm_src[s] ----
// one warp per dst node, lane handles 4 contiguous features (float4)
__global__ __launch_bounds__(256) void gather_kernel(const float* __restrict__ x)
{
    int warp = (blockIdx.x * blockDim.x + threadIdx.x) >> 5;
    int lane = threadIdx.x & 31;
    if (warp >= N_NODES) return;
    int beg = g_row_ptr[warp];
    int end = g_row_ptr[warp + 1];
    float4 acc = make_float4(0.f, 0.f, 0.f, 0.f);
    for (int j = beg; j < end; j++) {
        int s = g_csr_src[j];
        float ns = g_norm_src[s];
        float4 v = reinterpret_cast<const float4*>(x + (size_t)s * IN_F)[lane];
        acc.x = fmaf(v.x, ns, acc.x);
        acc.y = fmaf(v.y, ns, acc.y);
        acc.z = fmaf(v.z, ns, acc.z);
        acc.w = fmaf(v.w, ns, acc.w);
    }
    float nd = g_norm_dst[warp];
    acc.x *= nd; acc.y *= nd; acc.z *= nd; acc.w *= nd;
    reinterpret_cast<float4*>(g_agg + (size_t)warp * IN_F)[lane] = acc;
}

// ---------------- tf32 tensor-core GEMM: C = op(A) @ B + bias ------------------
// BM=128, BN=128, BK=32. 256 threads = 8 warps as 4(m) x 2(n); warp tile 32x64.
// mma.sync.aligned.m16n8k8 tf32, fp32 accumulate.
__device__ __forceinline__ uint32_t f2tf(float f) {
    uint32_t u;
    asm("cvt.rna.tf32.f32 %0, %1;" : "=r"(u) : "f"(f));
    return u;
}

template <bool RELU_A>
__global__ __launch_bounds__(256) void gemm_tf32(
    const float* __restrict__ A, const float* __restrict__ B,
    const float* __restrict__ bias, float* __restrict__ C,
    int M, int K, int NC)
{
    constexpr int BM = 128, BN = 128, BK = 32;
    constexpr int AS = BK + 4;    // 36-word row stride (conflict-free frag LDS)
    constexpr int BS = BN + 8;    // 136-word row stride
    __shared__ uint32_t As[BM * AS];   // 18432 B
    __shared__ uint32_t Bs[BK * BS];   // 17408 B

    const int tid  = threadIdx.x;
    const int lane = tid & 31;
    const int wrp  = tid >> 5;
    const int wm   = wrp & 3;          // 0..3: m offset wm*32
    const int wn   = wrp >> 2;         // 0..1: n offset wn*64
    const int gid  = lane >> 2;        // groupID 0..7
    const int tig  = lane & 3;         // threadID in group 0..3

    const int block_m = blockIdx.y * BM;
    const int block_n = blockIdx.x * BN;

    // global load mapping
    const int a_row = tid >> 3;        // 0..31, +32*i  (4 iters -> 128 rows)
    const int a_c4  = tid & 7;         // float4 column within BK=32
    const int b_row = tid >> 5;        // 0..7, +8*i   (4 iters -> 32 rows)
    const int b_c4  = tid & 31;        // float4 column within BN=128

    const int nchunks = K / BK;

    float acc[64];
    #pragma unroll
    for (int i = 0; i < 64; i++) acc[i] = 0.0f;

    float4 a_pref[4], b_pref[4];

    auto load_tile = [&](int k0) {
        #pragma unroll
        for (int i = 0; i < 4; i++) {
            int gr = block_m + a_row + i * 32;
            if (gr < M)
                a_pref[i] = reinterpret_cast<const float4*>(
                                A + (size_t)gr * K + k0)[a_c4];
            else
                a_pref[i] = make_float4(0.f, 0.f, 0.f, 0.f);
        }
        #pragma unroll
        for (int i = 0; i < 4; i++) {
            b_pref[i] = reinterpret_cast<const float4*>(
                            B + (size_t)(k0 + b_row + i * 8) * NC + block_n)[b_c4];
        }
    };

    auto store_tile = [&]() {
        #pragma unroll
        for (int i = 0; i < 4; i++) {
            float4 v = a_pref[i];
            if (RELU_A) {
                v.x = fmaxf(v.x, 0.f); v.y = fmaxf(v.y, 0.f);
                v.z = fmaxf(v.z, 0.f); v.w = fmaxf(v.w, 0.f);
            }
            uint4 u = make_uint4(f2tf(v.x), f2tf(v.y), f2tf(v.z), f2tf(v.w));
            *reinterpret_cast<uint4*>(&As[(a_row + i * 32) * AS + a_c4 * 4]) = u;
        }
        #pragma unroll
        for (int i = 0; i < 4; i++) {
            float4 v = b_pref[i];
            uint4 u = make_uint4(f2tf(v.x), f2tf(v.y), f2tf(v.z), f2tf(v.w));
            *reinterpret_cast<uint4*>(&Bs[(b_row + i * 8) * BS + b_c4 * 4]) = u;
        }
    };

    load_tile(0);

    for (int ch = 0; ch < nchunks; ch++) {
        store_tile();
        __syncthreads();
        if (ch + 1 < nchunks) load_tile((ch + 1) * BK);

        #pragma unroll
        for (int kq = 0; kq < 4; kq++) {
            uint32_t af[2][4];
            #pragma unroll
            for (int mt = 0; mt < 2; mt++) {
                int r = wm * 32 + mt * 16 + gid;
                int c = kq * 8 + tig;
                af[mt][0] = As[r * AS + c];
                af[mt][1] = As[(r + 8) * AS + c];
                af[mt][2] = As[r * AS + c + 4];
                af[mt][3] = As[(r + 8) * AS + c + 4];
            }
            uint32_t bf[8][2];
            #pragma unroll
            for (int nt = 0; nt < 8; nt++) {
                int cb = wn * 64 + nt * 8 + gid;
                int rb = kq * 8 + tig;
                bf[nt][0] = Bs[rb * BS + cb];
                bf[nt][1] = Bs[(rb + 4) * BS + cb];
            }
            #pragma unroll
            for (int mt = 0; mt < 2; mt++) {
                #pragma unroll
                for (int nt = 0; nt < 8; nt++) {
                    float* c = &acc[(mt * 8 + nt) * 4];
                    asm volatile(
                        "mma.sync.aligned.m16n8k8.row.col.f32.tf32.tf32.f32 "
                        "{%0,%1,%2,%3},{%4,%5,%6,%7},{%8,%9},{%0,%1,%2,%3};\n"
                        : "+f"(c[0]), "+f"(c[1]), "+f"(c[2]), "+f"(c[3])
                        : "r"(af[mt][0]), "r"(af[mt][1]),
                          "r"(af[mt][2]), "r"(af[mt][3]),
                          "r"(bf[nt][0]), "r"(bf[nt][1]));
                }
            }
        }
        __syncthreads();
    }

    // epilogue: bias add + store
    #pragma unroll
    for (int mt = 0; mt < 2; mt++) {
        int r0 = block_m + wm * 32 + mt * 16 + gid;
        #pragma unroll
        for (int nt = 0; nt < 8; nt++) {
            int gc = block_n + wn * 64 + nt * 8 + tig * 2;
            float bv0 = bias[gc], bv1 = bias[gc + 1];
            const float* c = &acc[(mt * 8 + nt) * 4];
            if (r0 < M) {
                C[(size_t)r0 * NC + gc]     = c[0] + bv0;
                C[(size_t)r0 * NC + gc + 1] = c[1] + bv1;
            }
            if (r0 + 8 < M) {
                C[(size_t)(r0 + 8) * NC + gc]     = c[2] + bv0;
                C[(size_t)(r0 + 8) * NC + gc + 1] = c[3] + bv1;
            }
        }
    }
}

// ---------------- launch ------------------------------------------------------
extern "C" void kernel_launch(void* const* d_in, const int* in_sizes, int n_in,
                              void* d_out, int out_size)
{
    const float* x      = (const float*)d_in[0];   // [N, 128]
    const int*   src    = (const int*)  d_in[1];   // [E]
    const int*   dst    = (const int*)  d_in[2];   // [E]
    const float* W_conv = (const float*)d_in[3];   // [128, 256]
    const float* b_conv = (const float*)d_in[4];   // [256]
    const float* W_fc   = (const float*)d_in[5];   // [256, 256]
    const float* b_fc   = (const float*)d_in[6];   // [256]
    const float* W_fc2  = (const float*)d_in[7];   // [256, 256]
    const float* b_fc2  = (const float*)d_in[8];   // [256]
    float* out = (float*)d_out;                    // [N, 256]

    (void)in_sizes; (void)n_in; (void)out_size;

    float* agg_ptr; cudaGetSymbolAddress((void**)&agg_ptr, g_agg);
    float* h1_ptr;  cudaGetSymbolAddress((void**)&h1_ptr,  g_h1);
    float* h2_ptr;  cudaGetSymbolAddress((void**)&h2_ptr,  g_h2);

    const int NB = (N_NODES + 255) / 256;
    const int EB = (N_EDGES + 255) / 256;

    zero_kernel<<<NB, 256>>>();
    degree_kernel<<<EB, 256>>>(src, dst);
    norm_kernel<<<NB, 256>>>();
    scan_kernel<<<1, 1024>>>();
    cursor_kernel<<<NB, 256>>>();
    fill_kernel<<<EB, 256>>>(src, dst);

    // SpMM gather: one warp per dst node (8 warps/block)
    gather_kernel<<<(N_NODES + 7) / 8, 256>>>(x);

    dim3 grid(H_F / 128, (N_NODES + 127) / 128);
    // h1 = agg @ W_conv + b_conv       (norm_dst already folded into agg)
    gemm_tf32<false><<<grid, 256>>>(agg_ptr, W_conv, b_conv, h1_ptr,
                                    N_NODES, IN_F, H_F);
    // h2 = relu(h1) @ W_fc + b_fc
    gemm_tf32<true><<<grid, 256>>>(h1_ptr, W_fc, b_fc, h2_ptr,
                                   N_NODES, H_F, H_F);
    // out = relu(h2) @ W_fc2 + b_fc2
    gemm_tf32<true><<<grid, 256>>>(h2_ptr, W_fc2, b_fc2, out,
                                   N_NODES, H_F, H_F);
}

// round 4
// speedup vs baseline: 2.7263x; 1.1047x over previous
#include <cuda_runtime.h>
#include <cstdint>

#define N_NODES 50000
#define N_EDGES 600000
#define IN_F    128
#define H_F     256
#define NSB     ((N_NODES + 255) / 256)   // 196 scan blocks

// ---------------- scratch (static device globals; no allocation) -------------
__device__ int   g_deg_out_i[N_NODES];
__device__ int   g_deg_in_i[N_NODES];
__device__ float g_norm_src[N_NODES];
__device__ float g_norm_dst[N_NODES];
__device__ int   g_row_ptr[N_NODES + 1];
__device__ int   g_cursor[N_NODES];
__device__ int   g_csr_src[N_EDGES];
__device__ int   g_block_sums[NSB];
__device__ float g_agg[(size_t)N_NODES * IN_F];
__device__ float g_h1[(size_t)N_NODES * H_F];
__device__ float g_h2[(size_t)N_NODES * H_F];

// ---------------- zero degree counters ----------------------------------------
__global__ void zero_kernel() {
    int i = blockIdx.x * blockDim.x + threadIdx.x;
    if (i < N_NODES) { g_deg_out_i[i] = 0; g_deg_in_i[i] = 0; }
}

// ---------------- degree accumulation (int atomics) ----------------------------
__global__ void degree_kernel(const int* __restrict__ src,
                              const int* __restrict__ dst) {
    int e = blockIdx.x * blockDim.x + threadIdx.x;
    if (e >= N_EDGES) return;
    atomicAdd(&g_deg_out_i[src[e]], 1);
    atomicAdd(&g_deg_in_i[dst[e]], 1);
}

// ---------------- 3-phase parallel scan of deg_in -> row_ptr ------------------
// Phase A: per-block (256 elems) sum -> g_block_sums[b]
__global__ void scan_phaseA() {
    __shared__ int ws[8];
    int t = threadIdx.x, lane = t & 31, wid = t >> 5;
    int i = blockIdx.x * 256 + t;
    int v = (i < N_NODES) ? g_deg_in_i[i] : 0;
    #pragma unroll
    for (int off = 16; off > 0; off >>= 1)
        v += __shfl_down_sync(0xffffffffu, v, off);
    if (lane == 0) ws[wid] = v;
    __syncthreads();
    if (t == 0) {
        int s = 0;
        #pragma unroll
        for (int w = 0; w < 8; w++) s += ws[w];
        g_block_sums[blockIdx.x] = s;
    }
}

// Phase B: single block scans the 196 block sums -> exclusive offsets in place
__global__ void scan_phaseB() {
    __shared__ int ws[8];
    int t = threadIdx.x, lane = t & 31, wid = t >> 5;
    int v = (t < NSB) ? g_block_sums[t] : 0;
    int x = v;
    #pragma unroll
    for (int off = 1; off < 32; off <<= 1) {
        int tm = __shfl_up_sync(0xffffffffu, x, off);
        if (lane >= off) x += tm;
    }
    if (lane == 31) ws[wid] = x;
    __syncthreads();
    int add = 0;
    for (int w = 0; w < wid; w++) add += ws[w];
    if (t < NSB) g_block_sums[t] = x + add - v;   // exclusive
}

// Phase C: local inclusive scan + block offset; also emits cursor + norms
__global__ void scan_phaseC() {
    __shared__ int ws[8];
    int t = threadIdx.x, lane = t & 31, wid = t >> 5;
    int i = blockIdx.x * 256 + t;
    int v = (i < N_NODES) ? g_deg_in_i[i] : 0;
    int x = v;
    #pragma unroll
    for (int off = 1; off < 32; off <<= 1) {
        int tm = __shfl_up_sync(0xffffffffu, x, off);
        if (lane >= off) x += tm;
    }
    if (lane == 31) ws[wid] = x;
    __syncthreads();
    int add = 0;
    for (int w = 0; w < wid; w++) add += ws[w];
    int incl = x + add + g_block_sums[blockIdx.x];
    if (i < N_NODES) {
        g_row_ptr[i + 1] = incl;
        g_cursor[i] = incl - v;
        g_norm_src[i] = rsqrtf(fmaxf((float)g_deg_out_i[i], 1.0f));
        g_norm_dst[i] = rsqrtf(fmaxf((float)g_deg_in_i[i], 1.0f));
        if (i == 0) g_row_ptr[0] = 0;
    }
}

// ---------------- fill CSR (by dst) --------------------------------------------
__global__ void fill_kernel(const int* __restrict__ src,
                            const int* __restrict__ dst) {
    int e = blockIdx.x * blockDim.x + threadIdx.x;
    if (e >= N_EDGES) return;
    int pos = atomicAdd(&g_cursor[dst[e]], 1);
    g_csr_src[pos] = src[e];
}

// ---------------- gather SpMM: agg[d] = norm_dst[d] * sum x[s]*norm_src[s] ----
// one warp per dst node, lane handles 4 contiguous features (float4)
__global__ __launch_bounds__(256) void gather_kernel(const float* __restrict__ x)
{
    int warp = (blockIdx.x * blockDim.x + threadIdx.x) >> 5;
    int lane = threadIdx.x & 31;
    if (warp >= N_NODES) return;
    int beg = g_row_ptr[warp];
    int end = g_row_ptr[warp + 1];
    float4 acc = make_float4(0.f, 0.f, 0.f, 0.f);
    for (int j = beg; j < end; j++) {
        int s = g_csr_src[j];
        float ns = g_norm_src[s];
        float4 v = reinterpret_cast<const float4*>(x + (size_t)s * IN_F)[lane];
        acc.x = fmaf(v.x, ns, acc.x);
        acc.y = fmaf(v.y, ns, acc.y);
        acc.z = fmaf(v.z, ns, acc.z);
        acc.w = fmaf(v.w, ns, acc.w);
    }
    float nd = g_norm_dst[warp];
    acc.x *= nd; acc.y *= nd; acc.z *= nd; acc.w *= nd;
    reinterpret_cast<float4*>(g_agg + (size_t)warp * IN_F)[lane] = acc;
}

// ---------------- tf32 tensor-core GEMM: C = op(A) @ B + bias ------------------
// BM=128, BN=128, BK=32. 256 threads = 8 warps as 4(m) x 2(n); warp tile 32x64.
// mma.sync.aligned.m16n8k8 tf32, fp32 accumulate.
__device__ __forceinline__ uint32_t f2tf(float f) {
    uint32_t u;
    asm("cvt.rna.tf32.f32 %0, %1;" : "=r"(u) : "f"(f));
    return u;
}

template <bool RELU_A>
__global__ __launch_bounds__(256) void gemm_tf32(
    const float* __restrict__ A, const float* __restrict__ B,
    const float* __restrict__ bias, float* __restrict__ C,
    int M, int K, int NC)
{
    constexpr int BM = 128, BN = 128, BK = 32;
    constexpr int AS = BK + 4;    // 36-word row stride (conflict-free frag LDS)
    constexpr int BS = BN + 8;    // 136-word row stride
    __shared__ uint32_t As[BM * AS];   // 18432 B
    __shared__ uint32_t Bs[BK * BS];   // 17408 B

    const int tid  = threadIdx.x;
    const int lane = tid & 31;
    const int wrp  = tid >> 5;
    const int wm   = wrp & 3;          // 0..3: m offset wm*32
    const int wn   = wrp >> 2;         // 0..1: n offset wn*64
    const int gid  = lane >> 2;        // groupID 0..7
    const int tig  = lane & 3;         // threadID in group 0..3

    const int block_m = blockIdx.y * BM;
    const int block_n = blockIdx.x * BN;

    // global load mapping
    const int a_row = tid >> 3;        // 0..31, +32*i  (4 iters -> 128 rows)
    const int a_c4  = tid & 7;         // float4 column within BK=32
    const int b_row = tid >> 5;        // 0..7, +8*i   (4 iters -> 32 rows)
    const int b_c4  = tid & 31;        // float4 column within BN=128

    const int nchunks = K / BK;

    float acc[64];
    #pragma unroll
    for (int i = 0; i < 64; i++) acc[i] = 0.0f;

    float4 a_pref[4], b_pref[4];

    auto load_tile = [&](int k0) {
        #pragma unroll
        for (int i = 0; i < 4; i++) {
            int gr = block_m + a_row + i * 32;
            if (gr < M)
                a_pref[i] = reinterpret_cast<const float4*>(
                                A + (size_t)gr * K + k0)[a_c4];
            else
                a_pref[i] = make_float4(0.f, 0.f, 0.f, 0.f);
        }
        #pragma unroll
        for (int i = 0; i < 4; i++) {
            b_pref[i] = reinterpret_cast<const float4*>(
                            B + (size_t)(k0 + b_row + i * 8) * NC + block_n)[b_c4];
        }
    };

    auto store_tile = [&]() {
        #pragma unroll
        for (int i = 0; i < 4; i++) {
            float4 v = a_pref[i];
            if (RELU_A) {
                v.x = fmaxf(v.x, 0.f); v.y = fmaxf(v.y, 0.f);
                v.z = fmaxf(v.z, 0.f); v.w = fmaxf(v.w, 0.f);
            }
            uint4 u = make_uint4(f2tf(v.x), f2tf(v.y), f2tf(v.z), f2tf(v.w));
            *reinterpret_cast<uint4*>(&As[(a_row + i * 32) * AS + a_c4 * 4]) = u;
        }
        #pragma unroll
        for (int i = 0; i < 4; i++) {
            float4 v = b_pref[i];
            uint4 u = make_uint4(f2tf(v.x), f2tf(v.y), f2tf(v.z), f2tf(v.w));
            *reinterpret_cast<uint4*>(&Bs[(b_row + i * 8) * BS + b_c4 * 4]) = u;
        }
    };

    load_tile(0);

    for (int ch = 0; ch < nchunks; ch++) {
        store_tile();
        __syncthreads();
        if (ch + 1 < nchunks) load_tile((ch + 1) * BK);

        #pragma unroll
        for (int kq = 0; kq < 4; kq++) {
            uint32_t af[2][4];
            #pragma unroll
            for (int mt = 0; mt < 2; mt++) {
                int r = wm * 32 + mt * 16 + gid;
                int c = kq * 8 + tig;
                af[mt][0] = As[r * AS + c];
                af[mt][1] = As[(r + 8) * AS + c];
                af[mt][2] = As[r * AS + c + 4];
                af[mt][3] = As[(r + 8) * AS + c + 4];
            }
            uint32_t bf[8][2];
            #pragma unroll
            for (int nt = 0; nt < 8; nt++) {
                int cb = wn * 64 + nt * 8 + gid;
                int rb = kq * 8 + tig;
                bf[nt][0] = Bs[rb * BS + cb];
                bf[nt][1] = Bs[(rb + 4) * BS + cb];
            }
            #pragma unroll
            for (int mt = 0; mt < 2; mt++) {
                #pragma unroll
                for (int nt = 0; nt < 8; nt++) {
                    float* c = &acc[(mt * 8 + nt) * 4];
                    asm volatile(
                        "mma.sync.aligned.m16n8k8.row.col.f32.tf32.tf32.f32 "
                        "{%0,%1,%2,%3},{%4,%5,%6,%7},{%8,%9},{%0,%1,%2,%3};\n"
                        : "+f"(c[0]), "+f"(c[1]), "+f"(c[2]), "+f"(c[3])
                        : "r"(af[mt][0]), "r"(af[mt][1]),
                          "r"(af[mt][2]), "r"(af[mt][3]),
                          "r"(bf[nt][0]), "r"(bf[nt][1]));
                }
            }
        }
        __syncthreads();
    }

    // epilogue: bias add + store
    #pragma unroll
    for (int mt = 0; mt < 2; mt++) {
        int r0 = block_m + wm * 32 + mt * 16 + gid;
        #pragma unroll
        for (int nt = 0; nt < 8; nt++) {
            int gc = block_n + wn * 64 + nt * 8 + tig * 2;
            float bv0 = bias[gc], bv1 = bias[gc + 1];
            const float* c = &acc[(mt * 8 + nt) * 4];
            if (r0 < M) {
                C[(size_t)r0 * NC + gc]     = c[0] + bv0;
                C[(size_t)r0 * NC + gc + 1] = c[1] + bv1;
            }
            if (r0 + 8 < M) {
                C[(size_t)(r0 + 8) * NC + gc]     = c[2] + bv0;
                C[(size_t)(r0 + 8) * NC + gc + 1] = c[3] + bv1;
            }
        }
    }
}

// ---------------- launch ------------------------------------------------------
extern "C" void kernel_launch(void* const* d_in, const int* in_sizes, int n_in,
                              void* d_out, int out_size)
{
    const float* x      = (const float*)d_in[0];   // [N, 128]
    const int*   src    = (const int*)  d_in[1];   // [E]
    const int*   dst    = (const int*)  d_in[2];   // [E]
    const float* W_conv = (const float*)d_in[3];   // [128, 256]
    const float* b_conv = (const float*)d_in[4];   // [256]
    const float* W_fc   = (const float*)d_in[5];   // [256, 256]
    const float* b_fc   = (const float*)d_in[6];   // [256]
    const float* W_fc2  = (const float*)d_in[7];   // [256, 256]
    const float* b_fc2  = (const float*)d_in[8];   // [256]
    float* out = (float*)d_out;                    // [N, 256]

    (void)in_sizes; (void)n_in; (void)out_size;

    float* agg_ptr; cudaGetSymbolAddress((void**)&agg_ptr, g_agg);
    float* h1_ptr;  cudaGetSymbolAddress((void**)&h1_ptr,  g_h1);
    float* h2_ptr;  cudaGetSymbolAddress((void**)&h2_ptr,  g_h2);

    const int NB = (N_NODES + 255) / 256;
    const int EB = (N_EDGES + 255) / 256;

    zero_kernel<<<NB, 256>>>();
    degree_kernel<<<EB, 256>>>(src, dst);

    // parallel scan (replaces single-block scan; also emits cursor + norms)
    scan_phaseA<<<NSB, 256>>>();
    scan_phaseB<<<1, 256>>>();
    scan_phaseC<<<NSB, 256>>>();

    fill_kernel<<<EB, 256>>>(src, dst);

    // SpMM gather: one warp per dst node (8 warps/block)
    gather_kernel<<<(N_NODES + 7) / 8, 256>>>(x);

    dim3 grid(H_F / 128, (N_NODES + 127) / 128);
    // h1 = agg @ W_conv + b_conv       (norm_dst already folded into agg)
    gemm_tf32<false><<<grid, 256>>>(agg_ptr, W_conv, b_conv, h1_ptr,
                                    N_NODES, IN_F, H_F);
    // h2 = relu(h1) @ W_fc + b_fc
    gemm_tf32<true><<<grid, 256>>>(h1_ptr, W_fc, b_fc, h2_ptr,
                                   N_NODES, H_F, H_F);
    // out = relu(h2) @ W_fc2 + b_fc2
    gemm_tf32<true><<<grid, 256>>>(h2_ptr, W_fc2, b_fc2, out,
                                   N_NODES, H_F, H_F);
}

// round 7
// speedup vs baseline: 3.8161x; 1.3997x over previous
#include <cuda_runtime.h>
#include <cstdint>

#define N_NODES 50000
#define N_EDGES 600000
#define IN_F    128
#define H_F     256
#define NSB     ((N_NODES + 255) / 256)   // 196 scan blocks

// ---------------- scratch (static device globals; no allocation) -------------
__device__ int   g_deg_out_i[N_NODES];
__device__ int   g_deg_in_i[N_NODES];
__device__ float g_norm_src[N_NODES];
__device__ float g_norm_dst[N_NODES];
__device__ int   g_row_ptr[N_NODES + 1];
__device__ int   g_cursor[N_NODES];
__device__ int   g_csr_src[N_EDGES];
__device__ int   g_block_sums[NSB];
// agg padded by 128 rows so the last CTA's cp.async tile reads stay in-bounds
__device__ __align__(16) float g_agg[(size_t)(N_NODES + 128) * IN_F];
// tf32-pre-rounded weights, original row-major [K, 256]
__device__ __align__(16) float g_Wc_r[IN_F * H_F];
__device__ __align__(16) float g_Wf_r[H_F * H_F];
__device__ __align__(16) float g_Wf2_r[H_F * H_F];

// ---------------- helpers -------------------------------------------------------
__device__ __forceinline__ uint32_t f2tf(float f) {
    uint32_t u;
    asm("cvt.rna.tf32.f32 %0, %1;" : "=r"(u) : "f"(f));
    return u;
}
__device__ __forceinline__ uint32_t smem_to_u32(const void* p) {
    uint32_t a;
    asm("{ .reg .u64 t; cvta.to.shared.u64 t, %1; cvt.u32.u64 %0, t; }"
        : "=r"(a) : "l"(p));
    return a;
}
__device__ __forceinline__ void cp16(uint32_t saddr, const void* g) {
    asm volatile("cp.async.cg.shared.global [%0], [%1], 16;"
                 :: "r"(saddr), "l"(g) : "memory");
}
#define CP_COMMIT() asm volatile("cp.async.commit_group;" ::: "memory")
#define CP_WAIT0()  asm volatile("cp.async.wait_group 0;" ::: "memory")
#define CP_WAIT1()  asm volatile("cp.async.wait_group 1;" ::: "memory")

// ---------------- zero degree counters ----------------------------------------
__global__ void zero_kernel() {
    int i = blockIdx.x * blockDim.x + threadIdx.x;
    if (i < N_NODES) { g_deg_out_i[i] = 0; g_deg_in_i[i] = 0; }
}

// ---------------- weight tf32 pre-round (row-major, no transpose) -------------
__global__ void prep_weights(const float* __restrict__ Wc,
                             const float* __restrict__ Wf,
                             const float* __restrict__ Wf2) {
    int i = blockIdx.x * blockDim.x + threadIdx.x;
    const int S1 = IN_F * H_F, S2 = H_F * H_F;
    if (i < S1) { g_Wc_r[i] = __uint_as_float(f2tf(Wc[i])); return; }
    int j = i - S1;
    if (j < S2) { g_Wf_r[j] = __uint_as_float(f2tf(Wf[j])); return; }
    int l = j - S2;
    if (l < S2) { g_Wf2_r[l] = __uint_as_float(f2tf(Wf2[l])); }
}

// ---------------- degree accumulation ------------------------------------------
__global__ void degree_kernel(const int* __restrict__ src,
                              const int* __restrict__ dst) {
    int e = blockIdx.x * blockDim.x + threadIdx.x;
    if (e >= N_EDGES) return;
    atomicAdd(&g_deg_out_i[src[e]], 1);
    atomicAdd(&g_deg_in_i[dst[e]], 1);
}

// ---------------- 3-phase parallel scan of deg_in -> row_ptr ------------------
__global__ void scan_phaseA() {
    __shared__ int ws[8];
    int t = threadIdx.x, lane = t & 31, wid = t >> 5;
    int i = blockIdx.x * 256 + t;
    int v = (i < N_NODES) ? g_deg_in_i[i] : 0;
    #pragma unroll
    for (int off = 16; off > 0; off >>= 1)
        v += __shfl_down_sync(0xffffffffu, v, off);
    if (lane == 0) ws[wid] = v;
    __syncthreads();
    if (t == 0) {
        int s = 0;
        #pragma unroll
        for (int w = 0; w < 8; w++) s += ws[w];
        g_block_sums[blockIdx.x] = s;
    }
}
__global__ void scan_phaseB() {
    __shared__ int ws[8];
    int t = threadIdx.x, lane = t & 31, wid = t >> 5;
    int v = (t < NSB) ? g_block_sums[t] : 0;
    int x = v;
    #pragma unroll
    for (int off = 1; off < 32; off <<= 1) {
        int tm = __shfl_up_sync(0xffffffffu, x, off);
        if (lane >= off) x += tm;
    }
    if (lane == 31) ws[wid] = x;
    __syncthreads();
    int add = 0;
    for (int w = 0; w < wid; w++) add += ws[w];
    if (t < NSB) g_block_sums[t] = x + add - v;
}
__global__ void scan_phaseC() {
    __shared__ int ws[8];
    int t = threadIdx.x, lane = t & 31, wid = t >> 5;
    int i = blockIdx.x * 256 + t;
    int v = (i < N_NODES) ? g_deg_in_i[i] : 0;
    int x = v;
    #pragma unroll
    for (int off = 1; off < 32; off <<= 1) {
        int tm = __shfl_up_sync(0xffffffffu, x, off);
        if (lane >= off) x += tm;
    }
    if (lane == 31) ws[wid] = x;
    __syncthreads();
    int add = 0;
    for (int w = 0; w < wid; w++) add += ws[w];
    int incl = x + add + g_block_sums[blockIdx.x];
    if (i < N_NODES) {
        g_row_ptr[i + 1] = incl;
        g_cursor[i] = incl - v;
        g_norm_src[i] = rsqrtf(fmaxf((float)g_deg_out_i[i], 1.0f));
        g_norm_dst[i] = rsqrtf(fmaxf((float)g_deg_in_i[i], 1.0f));
        if (i == 0) g_row_ptr[0] = 0;
    }
}

// ---------------- fill CSR (by dst) --------------------------------------------
__global__ void fill_kernel(const int* __restrict__ src,
                            const int* __restrict__ dst) {
    int e = blockIdx.x * blockDim.x + threadIdx.x;
    if (e >= N_EDGES) return;
    int pos = atomicAdd(&g_cursor[dst[e]], 1);
    g_csr_src[pos] = src[e];
}

// ---------------- gather SpMM (agg output pre-rounded to tf32) -----------------
__global__ __launch_bounds__(256) void gather_kernel(const float* __restrict__ x)
{
    int warp = (blockIdx.x * blockDim.x + threadIdx.x) >> 5;
    int lane = threadIdx.x & 31;
    if (warp >= N_NODES) return;
    int beg = g_row_ptr[warp];
    int end = g_row_ptr[warp + 1];
    float4 acc = make_float4(0.f, 0.f, 0.f, 0.f);
    for (int j = beg; j < end; j++) {
        int s = g_csr_src[j];
        float ns = g_norm_src[s];
        float4 v = reinterpret_cast<const float4*>(x + (size_t)s * IN_F)[lane];
        acc.x = fmaf(v.x, ns, acc.x);
        acc.y = fmaf(v.y, ns, acc.y);
        acc.z = fmaf(v.z, ns, acc.z);
        acc.w = fmaf(v.w, ns, acc.w);
    }
    float nd = g_norm_dst[warp];
    float4 o;
    o.x = __uint_as_float(f2tf(acc.x * nd));
    o.y = __uint_as_float(f2tf(acc.y * nd));
    o.z = __uint_as_float(f2tf(acc.z * nd));
    o.w = __uint_as_float(f2tf(acc.w * nd));
    reinterpret_cast<float4*>(g_agg + (size_t)warp * IN_F)[lane] = o;
}

// ---------------- fused 3-GEMM MLP kernel ---------------------------------------
// One CTA owns 128 rows, computes:
//   h1 = agg_tile @ Wc + bc ; relu ; tf32-round  -> smem h-tile (A-chunk format)
//   h2 = h1 @ Wf + bf       ; relu ; tf32-round  -> smem h-tile (overwrite)
//   out = h2 @ Wf2 + bf2    -> global (fp32)
// A-chunk format: 8 slots of [128 rows x 36 words] (32 k-cols + 4 pad).
// B chunks: [32 k-rows x 264 words] (256 n-cols + 8 pad), double buffered.
// mma.sync.m16n8k8 tf32; 512 threads = 16 warps (4m x 4n), warp tile 32x64.

#define AS 36
#define BS 264
#define A_SLOT_W   (128 * AS)                 // 4608 words
#define H_BYTES    (8 * A_SLOT_W * 4)         // 147456
#define B_BYTES    (32 * BS * 4)              // 33792
#define B_OFF0     H_BYTES
#define B_OFF1     (H_BYTES + B_BYTES)
#define FUSED_SMEM (H_BYTES + 2 * B_BYTES)    // 215040

__device__ __forceinline__ void issue_B(uint32_t buf_saddr, const float* W,
                                        int k0, int tid) {
    #pragma unroll
    for (int it = 0; it < 4; it++) {
        int f = tid + it * 512;
        int row = f >> 6, c4 = f & 63;
        cp16(buf_saddr + (uint32_t)(row * BS + c4 * 4) * 4,
             W + (size_t)(k0 + row) * 256 + c4 * 4);
    }
}

__device__ __forceinline__ void mma_chunk(const uint32_t* __restrict__ Ach,
                                          const uint32_t* __restrict__ Bch,
                                          float* acc, int wm, int wn,
                                          int gid, int tig) {
    #pragma unroll
    for (int kq = 0; kq < 4; kq++) {
        uint32_t af[2][4];
        #pragma unroll
        for (int mt = 0; mt < 2; mt++) {
            int r = wm * 32 + mt * 16 + gid;
            int c = kq * 8 + tig;
            af[mt][0] = Ach[r * AS + c];
            af[mt][1] = Ach[(r + 8) * AS + c];
            af[mt][2] = Ach[r * AS + c + 4];
            af[mt][3] = Ach[(r + 8) * AS + c + 4];
        }
        uint32_t bfr[8][2];
        #pragma unroll
        for (int nt = 0; nt < 8; nt++) {
            int cb = wn * 64 + nt * 8 + gid;
            int rb = kq * 8 + tig;
            bfr[nt][0] = Bch[rb * BS + cb];
            bfr[nt][1] = Bch[(rb + 4) * BS + cb];
        }
        #pragma unroll
        for (int mt = 0; mt < 2; mt++) {
            #pragma unroll
            for (int nt = 0; nt < 8; nt++) {
                float* c = &acc[(mt * 8 + nt) * 4];
                asm volatile(
                    "mma.sync.aligned.m16n8k8.row.col.f32.tf32.tf32.f32 "
                    "{%0,%1,%2,%3},{%4,%5,%6,%7},{%8,%9},{%0,%1,%2,%3};\n"
                    : "+f"(c[0]), "+f"(c[1]), "+f"(c[2]), "+f"(c[3])
                    : "r"(af[mt][0]), "r"(af[mt][1]),
                      "r"(af[mt][2]), "r"(af[mt][3]),
                      "r"(bfr[nt][0]), "r"(bfr[nt][1]));
            }
        }
    }
}

__global__ void __launch_bounds__(512, 1) fused_mlp(
    const float* __restrict__ agg,
    const float* __restrict__ Wc,  const float* __restrict__ bc,
    const float* __restrict__ Wf,  const float* __restrict__ bf,
    const float* __restrict__ Wf2, const float* __restrict__ bf2,
    float* __restrict__ out, int M)
{
    extern __shared__ float sh[];
    const uint32_t sb = smem_to_u32(sh);
    const int tid  = threadIdx.x;
    const int lane = tid & 31;
    const int wrp  = tid >> 5;
    const int wm   = wrp & 3;
    const int wn   = wrp >> 2;
    const int gid  = lane >> 2;
    const int tig  = lane & 3;
    const int block_m = blockIdx.x * 128;

    float acc[64];
    #pragma unroll
    for (int i = 0; i < 64; i++) acc[i] = 0.0f;

    // -------- stage-1 prologue: agg tile (4 A-chunks into h slots 0..3) + B0 ---
    {
        int row = tid >> 3, c4 = tid & 7;
        #pragma unroll
        for (int ch = 0; ch < 4; ch++) {
            #pragma unroll
            for (int it = 0; it < 2; it++) {
                int r = row + it * 64;
                uint32_t d = sb + (uint32_t)(ch * A_SLOT_W + r * AS + c4 * 4) * 4;
                cp16(d, agg + (size_t)(block_m + r) * IN_F + ch * 32 + c4 * 4);
            }
        }
        issue_B(sb + B_OFF0, Wc, 0, tid);
        CP_COMMIT();
    }

    // -------- generic stage runner ------------------------------------------
    auto run_stage = [&](int NCH, const float* W) {
        for (int ch = 0; ch < NCH; ch++) {
            if (ch + 1 < NCH) {
                issue_B(sb + (((ch + 1) & 1) ? B_OFF1 : B_OFF0), W,
                        (ch + 1) * 32, tid);
                CP_COMMIT();
                CP_WAIT1();
            } else {
                CP_WAIT0();
            }
            __syncthreads();
            const uint32_t* Ach = (const uint32_t*)sh + ch * A_SLOT_W;
            const uint32_t* Bch = (const uint32_t*)((const char*)sh +
                                    ((ch & 1) ? B_OFF1 : B_OFF0));
            mma_chunk(Ach, Bch, acc, wm, wn, gid, tig);
            __syncthreads();
        }
    };

    // epilogue: acc -> h-tile slots (relu + tf32 round), then reset acc
    auto epilogue_h = [&](const float* bias) {
        uint32_t* hw = (uint32_t*)sh;
        #pragma unroll
        for (int mt = 0; mt < 2; mt++) {
            int r = wm * 32 + mt * 16 + gid;
            #pragma unroll
            for (int nt = 0; nt < 8; nt++) {
                int n = wn * 64 + nt * 8 + tig * 2;
                float b0 = bias[n], b1 = bias[n + 1];
                const float* c = &acc[(mt * 8 + nt) * 4];
                int base = (n >> 5) * A_SLOT_W + (n & 31);
                hw[base + r * AS]           = f2tf(fmaxf(c[0] + b0, 0.f));
                hw[base + r * AS + 1]       = f2tf(fmaxf(c[1] + b1, 0.f));
                hw[base + (r + 8) * AS]     = f2tf(fmaxf(c[2] + b0, 0.f));
                hw[base + (r + 8) * AS + 1] = f2tf(fmaxf(c[3] + b1, 0.f));
            }
        }
        #pragma unroll
        for (int i = 0; i < 64; i++) acc[i] = 0.0f;
    };

    // -------- stage 1: h1 = agg @ Wc (K=128) ----------------------------------
    run_stage(4, Wc);
    epilogue_h(bc);
    __syncthreads();

    // -------- stage 2: h2 = h1 @ Wf (K=256) -----------------------------------
    issue_B(sb + B_OFF0, Wf, 0, tid);
    CP_COMMIT();
    run_stage(8, Wf);
    epilogue_h(bf);
    __syncthreads();

    // -------- stage 3: out = h2 @ Wf2 (K=256) ---------------------------------
    issue_B(sb + B_OFF0, Wf2, 0, tid);
    CP_COMMIT();
    run_stage(8, Wf2);

    // final epilogue: bias add, fp32 store to global
    #pragma unroll
    for (int mt = 0; mt < 2; mt++) {
        int r0 = block_m + wm * 32 + mt * 16 + gid;
        #pragma unroll
        for (int nt = 0; nt < 8; nt++) {
            int n = wn * 64 + nt * 8 + tig * 2;
            float b0 = bf2[n], b1 = bf2[n + 1];
            const float* c = &acc[(mt * 8 + nt) * 4];
            if (r0 < M) {
                out[(size_t)r0 * 256 + n]     = c[0] + b0;
                out[(size_t)r0 * 256 + n + 1] = c[1] + b1;
            }
            if (r0 + 8 < M) {
                out[(size_t)(r0 + 8) * 256 + n]     = c[2] + b0;
                out[(size_t)(r0 + 8) * 256 + n + 1] = c[3] + b1;
            }
        }
    }
}

// ---------------- launch ------------------------------------------------------
extern "C" void kernel_launch(void* const* d_in, const int* in_sizes, int n_in,
                              void* d_out, int out_size)
{
    const float* x      = (const float*)d_in[0];
    const int*   src    = (const int*)  d_in[1];
    const int*   dst    = (const int*)  d_in[2];
    const float* W_conv = (const float*)d_in[3];
    const float* b_conv = (const float*)d_in[4];
    const float* W_fc   = (const float*)d_in[5];
    const float* b_fc   = (const float*)d_in[6];
    const float* W_fc2  = (const float*)d_in[7];
    const float* b_fc2  = (const float*)d_in[8];
    float* out = (float*)d_out;

    (void)in_sizes; (void)n_in; (void)out_size;

    float* agg_ptr; cudaGetSymbolAddress((void**)&agg_ptr, g_agg);
    float* wc_ptr;  cudaGetSymbolAddress((void**)&wc_ptr,  g_Wc_r);
    float* wf_ptr;  cudaGetSymbolAddress((void**)&wf_ptr,  g_Wf_r);
    float* wf2_ptr; cudaGetSymbolAddress((void**)&wf2_ptr, g_Wf2_r);

    static bool attr_done = false;
    if (!attr_done) {
        cudaFuncSetAttribute(fused_mlp,
                             cudaFuncAttributeMaxDynamicSharedMemorySize,
                             FUSED_SMEM);
        attr_done = true;
    }

    const int NB = (N_NODES + 255) / 256;
    const int EB = (N_EDGES + 255) / 256;

    zero_kernel<<<NB, 256>>>();
    prep_weights<<<(IN_F * H_F + 2 * H_F * H_F + 255) / 256, 256>>>(
        W_conv, W_fc, W_fc2);
    degree_kernel<<<EB, 256>>>(src, dst);

    scan_phaseA<<<NSB, 256>>>();
    scan_phaseB<<<1, 256>>>();
    scan_phaseC<<<NSB, 256>>>();

    fill_kernel<<<EB, 256>>>(src, dst);
    gather_kernel<<<(N_NODES + 7) / 8, 256>>>(x);

    const int GB = (N_NODES + 127) / 128;   // 391 CTAs
    fused_mlp<<<GB, 512, FUSED_SMEM>>>(agg_ptr,
                                       wc_ptr, b_conv,
                                       wf_ptr, b_fc,
                                       wf2_ptr, b_fc2,
                                       out, N_NODES);
}

// round 10
// speedup vs baseline: 4.9207x; 1.2894x over previous
#include <cuda_runtime.h>
#include <cuda_fp16.h>
#include <cstdint>

#define N_NODES 50000
#define N_EDGES 600000
#define IN_F    128
#define H_F     256
#define NSB     ((N_NODES + 255) / 256)   // 196 scan blocks

// ---------------- scratch (static device globals; no allocation) -------------
__device__ int   g_deg_out_i[N_NODES];
__device__ int   g_deg_in_i[N_NODES];
__device__ float g_norm_src[N_NODES];
__device__ float g_norm_dst[N_NODES];
__device__ int   g_row_ptr[N_NODES + 1];
__device__ int   g_cursor[N_NODES];
__device__ int   g_csr_src[N_EDGES];
__device__ int   g_block_sums[NSB];
// fp16 weights, transposed to [n][k] (k contiguous)
__device__ __align__(16) __half g_Wc_h[H_F * IN_F];
__device__ __align__(16) __half g_Wf_h[H_F * H_F];
__device__ __align__(16) __half g_Wf2_h[H_F * H_F];

// ---------------- helpers -------------------------------------------------------
__device__ __forceinline__ uint32_t smem_to_u32(const void* p) {
    uint32_t a;
    asm("{ .reg .u64 t; cvta.to.shared.u64 t, %1; cvt.u32.u64 %0, t; }"
        : "=r"(a) : "l"(p));
    return a;
}
__device__ __forceinline__ void cp16(uint32_t saddr, const void* g) {
    asm volatile("cp.async.cg.shared.global [%0], [%1], 16;"
                 :: "r"(saddr), "l"(g) : "memory");
}
#define CP_COMMIT() asm volatile("cp.async.commit_group;" ::: "memory")
#define CP_WAIT0()  asm volatile("cp.async.wait_group 0;" ::: "memory")
#define CP_WAIT1()  asm volatile("cp.async.wait_group 1;" ::: "memory")

// ---------------- init: zero degrees + fp16 transposed weights ----------------
__global__ void init_kernel(const float* __restrict__ Wc,
                            const float* __restrict__ Wf,
                            const float* __restrict__ Wf2) {
    int i = blockIdx.x * blockDim.x + threadIdx.x;
    if (i < N_NODES) { g_deg_out_i[i] = 0; g_deg_in_i[i] = 0; }
    if (i < H_F * IN_F) {
        int n = i / IN_F, k = i % IN_F;
        g_Wc_h[i] = __float2half_rn(Wc[k * H_F + n]);
    }
    if (i < H_F * H_F) {
        int n = i / H_F, k = i % H_F;
        g_Wf_h[i]  = __float2half_rn(Wf[k * H_F + n]);
        g_Wf2_h[i] = __float2half_rn(Wf2[k * H_F + n]);
    }
}

// ---------------- degree accumulation ------------------------------------------
__global__ void degree_kernel(const int* __restrict__ src,
                              const int* __restrict__ dst) {
    int e = blockIdx.x * blockDim.x + threadIdx.x;
    if (e >= N_EDGES) return;
    atomicAdd(&g_deg_out_i[src[e]], 1);
    atomicAdd(&g_deg_in_i[dst[e]], 1);
}

// ---------------- 3-phase parallel scan of deg_in -> row_ptr ------------------
__global__ void scan_phaseA() {
    __shared__ int ws[8];
    int t = threadIdx.x, lane = t & 31, wid = t >> 5;
    int i = blockIdx.x * 256 + t;
    int v = (i < N_NODES) ? g_deg_in_i[i] : 0;
    #pragma unroll
    for (int off = 16; off > 0; off >>= 1)
        v += __shfl_down_sync(0xffffffffu, v, off);
    if (lane == 0) ws[wid] = v;
    __syncthreads();
    if (t == 0) {
        int s = 0;
        #pragma unroll
        for (int w = 0; w < 8; w++) s += ws[w];
        g_block_sums[blockIdx.x] = s;
    }
}
__global__ void scan_phaseB() {
    __shared__ int ws[8];
    int t = threadIdx.x, lane = t & 31, wid = t >> 5;
    int v = (t < NSB) ? g_block_sums[t] : 0;
    int x = v;
    #pragma unroll
    for (int off = 1; off < 32; off <<= 1) {
        int tm = __shfl_up_sync(0xffffffffu, x, off);
        if (lane >= off) x += tm;
    }
    if (lane == 31) ws[wid] = x;
    __syncthreads();
    int add = 0;
    for (int w = 0; w < wid; w++) add += ws[w];
    if (t < NSB) g_block_sums[t] = x + add - v;
}
__global__ void scan_phaseC() {
    __shared__ int ws[8];
    int t = threadIdx.x, lane = t & 31, wid = t >> 5;
    int i = blockIdx.x * 256 + t;
    int v = (i < N_NODES) ? g_deg_in_i[i] : 0;
    int x = v;
    #pragma unroll
    for (int off = 1; off < 32; off <<= 1) {
        int tm = __shfl_up_sync(0xffffffffu, x, off);
        if (lane >= off) x += tm;
    }
    if (lane == 31) ws[wid] = x;
    __syncthreads();
    int add = 0;
    for (int w = 0; w < wid; w++) add += ws[w];
    int incl = x + add + g_block_sums[blockIdx.x];
    if (i < N_NODES) {
        g_row_ptr[i + 1] = incl;
        g_cursor[i] = incl - v;
        g_norm_src[i] = rsqrtf(fmaxf((float)g_deg_out_i[i], 1.0f));
        g_norm_dst[i] = rsqrtf(fmaxf((float)g_deg_in_i[i], 1.0f));
        if (i == 0) g_row_ptr[0] = 0;
    }
}

// ---------------- fill CSR (by dst) --------------------------------------------
__global__ void fill_kernel(const int* __restrict__ src,
                            const int* __restrict__ dst) {
    int e = blockIdx.x * blockDim.x + threadIdx.x;
    if (e >= N_EDGES) return;
    int pos = atomicAdd(&g_cursor[dst[e]], 1);
    g_csr_src[pos] = src[e];
}

// ---------------- fused gather + 3-GEMM MLP kernel ------------------------------
// One CTA owns 128 rows:
//   gather: A = norm_dst .* (sum_{src} x[src]*norm_src) -> smem A-tile (fp16)
//   h1 = A @ Wc + bc ; relu -> A-tile     (fp16, fp32 accum)
//   h2 = h1 @ Wf + bf ; relu -> A-tile
//   out = h2 @ Wf2 + bf2 -> global fp32
// A/h tile: 8 chunk-slots of [128 rows x 32 k] fp16, row stride 20 words (80B,
// 16B-aligned for cp.async; bank-conflict-free fragment LDS at stride 20).
// B tile: [256 n x 32 k] fp16, row stride 20 words; 3 rotating cp.async buffers.
// mma.sync.m16n8k16 f16/f32; 512 threads = 16 warps (4m x 4n), warp tile 32x64.

#define RS 20                               // words per 32-fp16 row (+4 pad)
#define CHW   (128 * RS)                    // A chunk words = 2560
#define H_W   (8 * CHW)                     // 20480 words = 81920 B
#define B_W   (256 * RS)                    // 5120 words  = 20480 B
#define FUSED_SMEM ((H_W + 3 * B_W) * 4)    // 143360 B = 140 KB

__device__ __forceinline__ void issue_B(uint32_t buf_saddr, const __half* W,
                                        int k0, int K, int tid) {
    #pragma unroll
    for (int it = 0; it < 2; it++) {
        int f = tid + it * 512;             // 0..1023
        int n = f >> 2, c = f & 3;
        cp16(buf_saddr + (uint32_t)(n * (RS * 4) + c * 16),
             W + (size_t)n * K + k0 + c * 8);
    }
}

__device__ __forceinline__ void mma_chunk(const uint32_t* __restrict__ Aw,
                                          const uint32_t* __restrict__ Bw,
                                          float* acc, int wm, int wn,
                                          int gid, int tig) {
    #pragma unroll
    for (int kq = 0; kq < 2; kq++) {
        uint32_t af[2][4];
        #pragma unroll
        for (int mt = 0; mt < 2; mt++) {
            int r = wm * 32 + mt * 16 + gid;
            int base = r * RS + kq * 8 + tig;
            af[mt][0] = Aw[base];
            af[mt][1] = Aw[base + 8 * RS];
            af[mt][2] = Aw[base + 4];
            af[mt][3] = Aw[base + 8 * RS + 4];
        }
        uint32_t bfr[8][2];
        #pragma unroll
        for (int nt = 0; nt < 8; nt++) {
            int n = wn * 64 + nt * 8 + gid;
            int bb = n * RS + kq * 8 + tig;
            bfr[nt][0] = Bw[bb];
            bfr[nt][1] = Bw[bb + 4];
        }
        #pragma unroll
        for (int mt = 0; mt < 2; mt++) {
            #pragma unroll
            for (int nt = 0; nt < 8; nt++) {
                float* c = &acc[(mt * 8 + nt) * 4];
                asm volatile(
                    "mma.sync.aligned.m16n8k16.row.col.f32.f16.f16.f32 "
                    "{%0,%1,%2,%3},{%4,%5,%6,%7},{%8,%9},{%0,%1,%2,%3};\n"
                    : "+f"(c[0]), "+f"(c[1]), "+f"(c[2]), "+f"(c[3])
                    : "r"(af[mt][0]), "r"(af[mt][1]),
                      "r"(af[mt][2]), "r"(af[mt][3]),
                      "r"(bfr[nt][0]), "r"(bfr[nt][1]));
            }
        }
    }
}

__global__ void __launch_bounds__(512, 1) fused_mlp(
    const float* __restrict__ x,
    const __half* __restrict__ Wc,  const float* __restrict__ bc,
    const __half* __restrict__ Wf,  const float* __restrict__ bf,
    const __half* __restrict__ Wf2, const float* __restrict__ bf2,
    float* __restrict__ out, int M)
{
    extern __shared__ uint32_t shw[];
    const uint32_t sb = smem_to_u32(shw);
    const int tid  = threadIdx.x;
    const int lane = tid & 31;
    const int wrp  = tid >> 5;
    const int wm   = wrp & 3;
    const int wn   = wrp >> 2;
    const int gid  = lane >> 2;
    const int tig  = lane & 3;
    const int block_m = blockIdx.x * 128;

    float acc[64];
    #pragma unroll
    for (int i = 0; i < 64; i++) acc[i] = 0.0f;

    // -------- prologue: prefetch B0 of stage 1, then gather into A tile -------
    issue_B(sb + H_W * 4, Wc, 0, IN_F, tid);
    CP_COMMIT();

    // gather: warp wrp handles rows wrp, wrp+16, ..., wrp+112
    #pragma unroll 1
    for (int rr = 0; rr < 8; rr++) {
        int r = rr * 16 + wrp;
        int grow = block_m + r;
        float4 a4 = make_float4(0.f, 0.f, 0.f, 0.f);
        if (grow < M) {
            int beg = g_row_ptr[grow];
            int end = g_row_ptr[grow + 1];
            for (int j = beg; j < end; j++) {
                int s = g_csr_src[j];
                float ns = g_norm_src[s];
                float4 v = reinterpret_cast<const float4*>(
                               x + (size_t)s * IN_F)[lane];
                a4.x = fmaf(v.x, ns, a4.x);
                a4.y = fmaf(v.y, ns, a4.y);
                a4.z = fmaf(v.z, ns, a4.z);
                a4.w = fmaf(v.w, ns, a4.w);
            }
            float nd = g_norm_dst[grow];
            a4.x *= nd; a4.y *= nd; a4.z *= nd; a4.w *= nd;
        }
        uint32_t w = (uint32_t)((lane >> 3) * CHW + r * RS + (lane & 7) * 2);
        __half2 h01 = __floats2half2_rn(a4.x, a4.y);
        __half2 h23 = __floats2half2_rn(a4.z, a4.w);
        *reinterpret_cast<__half2*>(&shw[w])     = h01;
        *reinterpret_cast<__half2*>(&shw[w + 1]) = h23;
    }

    // -------- generic stage runner: 3 B-buffers, one sync per chunk -----------
    auto run_stage = [&](int NCH, const __half* W, int K) {
        for (int ch = 0; ch < NCH; ch++) {
            if (ch + 1 < NCH) {
                issue_B(sb + (H_W + ((ch + 1) % 3) * B_W) * 4, W,
                        (ch + 1) * 32, K, tid);
                CP_COMMIT();
                CP_WAIT1();
            } else {
                CP_WAIT0();
            }
            __syncthreads();
            mma_chunk(shw + ch * CHW, shw + H_W + (ch % 3) * B_W,
                      acc, wm, wn, gid, tig);
        }
    };

    // epilogue: acc -> A tile (bias, relu, fp16), reset acc
    auto epilogue_h = [&](const float* bias) {
        #pragma unroll
        for (int mt = 0; mt < 2; mt++) {
            int r = wm * 32 + mt * 16 + gid;
            #pragma unroll
            for (int nt = 0; nt < 8; nt++) {
                int n = wn * 64 + nt * 8 + tig * 2;
                float b0 = bias[n], b1 = bias[n + 1];
                const float* c = &acc[(mt * 8 + nt) * 4];
                int wbase = (n >> 5) * CHW + ((n & 31) >> 1);
                __half2 lo = __floats2half2_rn(fmaxf(c[0] + b0, 0.f),
                                               fmaxf(c[1] + b1, 0.f));
                __half2 hi = __floats2half2_rn(fmaxf(c[2] + b0, 0.f),
                                               fmaxf(c[3] + b1, 0.f));
                *reinterpret_cast<__half2*>(&shw[wbase + r * RS])       = lo;
                *reinterpret_cast<__half2*>(&shw[wbase + (r + 8) * RS]) = hi;
            }
        }
        #pragma unroll
        for (int i = 0; i < 64; i++) acc[i] = 0.0f;
    };

    // -------- stage 1: h1 = A @ Wc (K=128) ------------------------------------
    run_stage(4, Wc, IN_F);
    __syncthreads();               // all mma done before A overwrite
    epilogue_h(bc);
    issue_B(sb + H_W * 4, Wf, 0, H_F, tid);
    CP_COMMIT();

    // -------- stage 2: h2 = h1 @ Wf (K=256) -----------------------------------
    run_stage(8, Wf, H_F);
    __syncthreads();
    epilogue_h(bf);
    issue_B(sb + H_W * 4, Wf2, 0, H_F, tid);
    CP_COMMIT();

    // -------- stage 3: out = h2 @ Wf2 (K=256) ---------------------------------
    run_stage(8, Wf2, H_F);

    // final epilogue: bias add, fp32 store
    #pragma unroll
    for (int mt = 0; mt < 2; mt++) {
        int r0 = block_m + wm * 32 + mt * 16 + gid;
        #pragma unroll
        for (int nt = 0; nt < 8; nt++) {
            int n = wn * 64 + nt * 8 + tig * 2;
            float b0 = bf2[n], b1 = bf2[n + 1];
            const float* c = &acc[(mt * 8 + nt) * 4];
            if (r0 < M) {
                out[(size_t)r0 * 256 + n]     = c[0] + b0;
                out[(size_t)r0 * 256 + n + 1] = c[1] + b1;
            }
            if (r0 + 8 < M) {
                out[(size_t)(r0 + 8) * 256 + n]     = c[2] + b0;
                out[(size_t)(r0 + 8) * 256 + n + 1] = c[3] + b1;
            }
        }
    }
}

// ---------------- launch ------------------------------------------------------
extern "C" void kernel_launch(void* const* d_in, const int* in_sizes, int n_in,
                              void* d_out, int out_size)
{
    const float* x      = (const float*)d_in[0];
    const int*   src    = (const int*)  d_in[1];
    const int*   dst    = (const int*)  d_in[2];
    const float* W_conv = (const float*)d_in[3];
    const float* b_conv = (const float*)d_in[4];
    const float* W_fc   = (const float*)d_in[5];
    const float* b_fc   = (const float*)d_in[6];
    const float* W_fc2  = (const float*)d_in[7];
    const float* b_fc2  = (const float*)d_in[8];
    float* out = (float*)d_out;

    (void)in_sizes; (void)n_in; (void)out_size;

    __half* wc_ptr;  cudaGetSymbolAddress((void**)&wc_ptr,  g_Wc_h);
    __half* wf_ptr;  cudaGetSymbolAddress((void**)&wf_ptr,  g_Wf_h);
    __half* wf2_ptr; cudaGetSymbolAddress((void**)&wf2_ptr, g_Wf2_h);

    static bool attr_done = false;
    if (!attr_done) {
        cudaFuncSetAttribute(fused_mlp,
                             cudaFuncAttributeMaxDynamicSharedMemorySize,
                             FUSED_SMEM);
        attr_done = true;
    }

    const int EB = (N_EDGES + 255) / 256;

    init_kernel<<<(H_F * H_F + 255) / 256, 256>>>(W_conv, W_fc, W_fc2);
    degree_kernel<<<EB, 256>>>(src, dst);

    scan_phaseA<<<NSB, 256>>>();
    scan_phaseB<<<1, 256>>>();
    scan_phaseC<<<NSB, 256>>>();

    fill_kernel<<<EB, 256>>>(src, dst);

    const int GB = (N_NODES + 127) / 128;   // 391 CTAs
    fused_mlp<<<GB, 512, FUSED_SMEM>>>(x,
                                       wc_ptr, b_conv,
                                       wf_ptr, b_fc,
                                       wf2_ptr, b_fc2,
                                       out, N_NODES);
}